// round 1
// baseline (speedup 1.0000x reference)
#include <cuda_runtime.h>
#include <math.h>

// Problem constants
#define BATCH 16384
#define DIM 4096
#define NUM_EXPERTS 64
#define TOP_K 2

// ---------------------------------------------------------------------------
// Router kernel: one warp per token row.
// softmax -> top2 -> renormalize  ==  top2 of logits, w = sigmoid(l1 - l2).
// Tie-break: lower index wins (matches jax.lax.top_k).
// Writes indices (as float) and weights into the tail of d_out.
// ---------------------------------------------------------------------------
__device__ __forceinline__ bool better(float v, int i, float w, int j) {
    return (v > w) || (v == w && i < j);
}

__global__ void router_top2_kernel(const float* __restrict__ logits,
                                   float* __restrict__ idx_out,
                                   float* __restrict__ w_out) {
    const int warps_per_block = blockDim.x >> 5;
    const int row = blockIdx.x * warps_per_block + (threadIdx.x >> 5);
    const int lane = threadIdx.x & 31;
    if (row >= BATCH) return;

    const float* l = logits + (size_t)row * NUM_EXPERTS;
    // each lane owns 2 experts: lane and lane+32
    float v0 = l[lane];
    float v1 = l[lane + 32];

    float a, b; int ai, bi;
    if (better(v0, lane, v1, lane + 32)) { a = v0; ai = lane;      b = v1; bi = lane + 32; }
    else                                 { a = v1; ai = lane + 32; b = v0; bi = lane; }

    // butterfly merge of (top, second) pairs — all lanes converge to same result
    #pragma unroll
    for (int off = 16; off > 0; off >>= 1) {
        float oa = __shfl_xor_sync(0xffffffffu, a, off);
        int  oai = __shfl_xor_sync(0xffffffffu, ai, off);
        float ob = __shfl_xor_sync(0xffffffffu, b, off);
        int  obi = __shfl_xor_sync(0xffffffffu, bi, off);

        float na, nb; int nai, nbi;
        if (better(a, ai, oa, oai)) {
            na = a; nai = ai;
            if (better(b, bi, oa, oai)) { nb = b;  nbi = bi; }
            else                        { nb = oa; nbi = oai; }
        } else {
            na = oa; nai = oai;
            if (better(a, ai, ob, obi)) { nb = a;  nbi = ai; }
            else                        { nb = ob; nbi = obi; }
        }
        a = na; ai = nai; b = nb; bi = nbi;
    }

    if (lane == 0) {
        // renormalized softmax over the top-2: exp(a)/(exp(a)+exp(b))
        float e = __expf(b - a);          // <= 1, no overflow
        float inv = 1.0f / (1.0f + e);
        float w1 = inv;
        float w2 = e * inv;
        idx_out[row * 2 + 0] = (float)ai;
        idx_out[row * 2 + 1] = (float)bi;
        w_out[row * 2 + 0] = w1;
        w_out[row * 2 + 1] = w2;
    }
}

// ---------------------------------------------------------------------------
// Expansion kernel: read each input float4 once, store it to BOTH replicated
// output rows (2t and 2t+1). DRAM read = 256 MB, write = 512 MB.
// ---------------------------------------------------------------------------
__global__ void expand_kernel(const float4* __restrict__ x,
                              float4* __restrict__ out) {
    // total input float4s: BATCH * (DIM/4) = 16384 * 1024 = 16,777,216
    const unsigned i = blockIdx.x * blockDim.x + threadIdx.x;
    const unsigned token = i >> 10;          // / 1024
    const unsigned col   = i & 1023;
    float4 v = __ldg(&x[i]);
    const size_t base = (size_t)token * 2048 + col;   // 2 output rows of 1024 f4
    out[base]        = v;
    out[base + 1024] = v;
}

extern "C" void kernel_launch(void* const* d_in, const int* in_sizes, int n_in,
                              void* d_out, int out_size) {
    const float* x      = (const float*)d_in[0];  // [16384, 4096]
    const float* logits = (const float*)d_in[1];  // [16384, 64]
    float* out = (float*)d_out;

    // output layout: [expanded_x (32768*4096) | indices (32768) | weights (32768)]
    const size_t expanded_elems = (size_t)BATCH * TOP_K * DIM;
    float* idx_out = out + expanded_elems;
    float* w_out   = idx_out + (size_t)BATCH * TOP_K;

    // Router: 8 warps per block (256 threads) -> 2048 blocks
    {
        const int threads = 256;
        const int warps_per_block = threads / 32;
        const int blocks = (BATCH + warps_per_block - 1) / warps_per_block;
        router_top2_kernel<<<blocks, threads>>>(logits, idx_out, w_out);
    }

    // Expansion: 16,777,216 float4 elements, 256 threads/block -> 65536 blocks
    {
        const int threads = 256;
        const unsigned total = (unsigned)BATCH * (DIM / 4);
        const unsigned blocks = total / threads;
        expand_kernel<<<blocks, threads>>>((const float4*)x, (float4*)out);
    }
}

// round 4
// speedup vs baseline: 1.0356x; 1.0356x over previous
#include <cuda_runtime.h>
#include <math.h>

#define BATCH 16384
#define DIM 4096
#define NUM_EXPERTS 64
#define TOP_K 2

// Output layout: [expanded_x (32768*4096) | indices (32768) | weights (32768)]

__device__ __forceinline__ bool better(float v, int i, float w, int j) {
    return (v > w) || (v == w && i < j);
}

// Fused kernel: 65536 blocks x 256 threads.
// Each thread copies one float4 of x to both replicated output rows.
// Every 4th block's warp 0 additionally computes the router top-2 for its row.
__global__ void __launch_bounds__(256) fused_dispatch_kernel(
    const float4* __restrict__ x,
    const float* __restrict__ logits,
    float4* __restrict__ out,
    float* __restrict__ idx_out,
    float* __restrict__ w_out) {

    const unsigned i = blockIdx.x * 256u + threadIdx.x;
    const unsigned token = i >> 10;          // / 1024 f4 per input row
    const unsigned col   = i & 1023;

    const bool is_router = ((blockIdx.x & 3u) == 0u) && (threadIdx.x < 32u);
    const int  row  = blockIdx.x >> 2;
    const int  lane = threadIdx.x;

    // Issue all loads up front so they overlap.
    float4 v = __ldcs(&x[i]);
    float v0 = 0.0f, v1 = 0.0f;
    if (is_router) {
        const float* l = logits + (size_t)row * NUM_EXPERTS;
        v0 = l[lane];
        v1 = l[lane + 32];
    }

    // streaming 16B stores (never re-read)
    const size_t base = (size_t)token * 2048 + col;  // 2 output rows of 1024 f4
    __stcs(&out[base],        v);
    __stcs(&out[base + 1024], v);

    if (is_router) {
        float a, b; int ai, bi;
        if (better(v0, lane, v1, lane + 32)) { a = v0; ai = lane;      b = v1; bi = lane + 32; }
        else                                 { a = v1; ai = lane + 32; b = v0; bi = lane; }

        #pragma unroll
        for (int off = 16; off > 0; off >>= 1) {
            float oa = __shfl_xor_sync(0xffffffffu, a, off);
            int  oai = __shfl_xor_sync(0xffffffffu, ai, off);
            float ob = __shfl_xor_sync(0xffffffffu, b, off);
            int  obi = __shfl_xor_sync(0xffffffffu, bi, off);

            float na, nb; int nai, nbi;
            if (better(a, ai, oa, oai)) {
                na = a; nai = ai;
                if (better(b, bi, oa, oai)) { nb = b;  nbi = bi; }
                else                        { nb = oa; nbi = oai; }
            } else {
                na = oa; nai = oai;
                if (better(a, ai, ob, obi)) { nb = a;  nbi = ai; }
                else                        { nb = ob; nbi = obi; }
            }
            a = na; ai = nai; b = nb; bi = nbi;
        }

        if (lane == 0) {
            // renormalized top-2 softmax: exp(a)/(exp(a)+exp(b)), exp(b)/(...)
            float e = __expf(b - a);          // <= 1, safe
            float inv = 1.0f / (1.0f + e);
            idx_out[row * 2 + 0] = (float)ai;
            idx_out[row * 2 + 1] = (float)bi;
            w_out[row * 2 + 0] = inv;
            w_out[row * 2 + 1] = e * inv;
        }
    }
}

extern "C" void kernel_launch(void* const* d_in, const int* in_sizes, int n_in,
                              void* d_out, int out_size) {
    const float* x      = (const float*)d_in[0];  // [16384, 4096]
    const float* logits = (const float*)d_in[1];  // [16384, 64]
    float* out = (float*)d_out;

    const size_t expanded_elems = (size_t)BATCH * TOP_K * DIM;
    float* idx_out = out + expanded_elems;
    float* w_out   = idx_out + (size_t)BATCH * TOP_K;

    const unsigned total_f4 = (unsigned)BATCH * (DIM / 4);  // 16,777,216
    const unsigned blocks = total_f4 / 256;                  // 65,536
    fused_dispatch_kernel<<<blocks, 256>>>((const float4*)x, logits,
                                           (float4*)out, idx_out, w_out);
}